// round 11
// baseline (speedup 1.0000x reference)
#include <cuda_runtime.h>
#include <cuda_bf16.h>
#include <cstdint>
#include <math.h>

// Problem constants
#define BATCH 2
#define SEQ   2048
#define HID   1024
#define NH    16
#define HD    64
#define MROWS (BATCH * SEQ)   // 4096

static const size_t OUT_ELEMS  = (size_t)BATCH * SEQ * HID;              // 4,194,304
static const size_t ATTN_ELEMS = (size_t)BATCH * NH * SEQ * (size_t)SEQ; // 134,217,728

// Scratch (allocation-free: __device__ globals)
__device__ __align__(16) float g_q[MROWS * HID];
__device__ __align__(16) float g_k[MROWS * HID];
__device__ __align__(16) float g_v[MROWS * HID];
__device__ __align__(16) float g_ctx[MROWS * HID];
__device__ __align__(16) float g_attn_scratch[(size_t)BATCH * NH * SEQ * (size_t)SEQ];

// bf16 hi/lo split scratch
__device__ __align__(16) __nv_bfloat16 g_ah[MROWS * HID];   // activations hi
__device__ __align__(16) __nv_bfloat16 g_al[MROWS * HID];   // activations lo
__device__ __align__(16) __nv_bfloat16 g_wh[4 * HID * HID]; // weights hi (q,k,v,o)
__device__ __align__(16) __nv_bfloat16 g_wl[4 * HID * HID]; // weights lo

// ---------------------------------------------------------------------------
// PTX helpers (baseline sm_80+ features only — no tcgen05 on this toolchain)
// ---------------------------------------------------------------------------
typedef unsigned long long ull;

__device__ __forceinline__ ull dup2(float a) {
    ull r; asm("mov.b64 %0, {%1, %1};" : "=l"(r) : "f"(a)); return r;
}
__device__ __forceinline__ ull pk2(float x, float y) {
    ull r; asm("mov.b64 %0, {%1, %2};" : "=l"(r) : "f"(x), "f"(y)); return r;
}
__device__ __forceinline__ void ffma2(ull& d, ull a, ull b) {
    asm("fma.rn.f32x2 %0, %1, %2, %3;" : "=l"(d) : "l"(a), "l"(b), "l"(d));
}
__device__ __forceinline__ float2 unp2(ull v) {
    float2 f; asm("mov.b64 {%0, %1}, %2;" : "=f"(f.x), "=f"(f.y) : "l"(v)); return f;
}

__device__ __forceinline__ uint32_t smem_u32(const void* p) {
    uint32_t a;
    asm("{ .reg .u64 t; cvta.to.shared.u64 t, %1; cvt.u32.u64 %0, t; }" : "=r"(a) : "l"(p));
    return a;
}

#define CP_ASYNC16(dst, src) \
    asm volatile("cp.async.cg.shared.global [%0], [%1], 16;" :: "r"(dst), "l"(src) : "memory")
#define CP_COMMIT() asm volatile("cp.async.commit_group;" ::: "memory")
#define CP_WAIT(N)  asm volatile("cp.async.wait_group %0;" :: "n"(N) : "memory")

#define LDM4(r, a)                                                              \
    asm volatile("ldmatrix.sync.aligned.m8n8.x4.shared.b16 {%0,%1,%2,%3}, [%4];" \
                 : "=r"((r)[0]), "=r"((r)[1]), "=r"((r)[2]), "=r"((r)[3]) : "r"(a))

#define MMA16816(c, a, b)                                                       \
    asm volatile("mma.sync.aligned.m16n8k16.row.col.f32.bf16.bf16.f32 "         \
                 "{%0,%1,%2,%3}, {%4,%5,%6,%7}, {%8,%9}, {%0,%1,%2,%3};"        \
                 : "+f"((c)[0]), "+f"((c)[1]), "+f"((c)[2]), "+f"((c)[3])       \
                 : "r"((a)[0]), "r"((a)[1]), "r"((a)[2]), "r"((a)[3]),          \
                   "r"((b)[0]), "r"((b)[1]))

// ---------------------------------------------------------------------------
// fp32 -> bf16 hi/lo split
// ---------------------------------------------------------------------------
__global__ __launch_bounds__(256) void conv_split(
    const float* __restrict__ src, __nv_bfloat16* __restrict__ hi,
    __nv_bfloat16* __restrict__ lo, int n)
{
    int i = (blockIdx.x * 256 + threadIdx.x) * 4;
    if (i >= n) return;
    float4 v = *(const float4*)&src[i];
    __nv_bfloat16 h0 = __float2bfloat16(v.x), h1 = __float2bfloat16(v.y);
    __nv_bfloat16 h2 = __float2bfloat16(v.z), h3 = __float2bfloat16(v.w);
    __nv_bfloat16 l0 = __float2bfloat16(v.x - __bfloat162float(h0));
    __nv_bfloat16 l1 = __float2bfloat16(v.y - __bfloat162float(h1));
    __nv_bfloat16 l2 = __float2bfloat16(v.z - __bfloat162float(h2));
    __nv_bfloat16 l3 = __float2bfloat16(v.w - __bfloat162float(h3));
    *(__nv_bfloat162*)&hi[i]     = __nv_bfloat162(h0, h1);
    *(__nv_bfloat162*)&hi[i + 2] = __nv_bfloat162(h2, h3);
    *(__nv_bfloat162*)&lo[i]     = __nv_bfloat162(l0, l1);
    *(__nv_bfloat162*)&lo[i + 2] = __nv_bfloat162(l2, l3);
}

// ---------------------------------------------------------------------------
// Tensor-core (mma.sync bf16) 3-split GEMM:
//   C[M,N] = Ah@Bh^T + Ah@Bl^T + Al@Bh^T + bias
// BM=128, BN=128, BK=32. 256 threads = 8 warps, warp tile 64x32.
// cp.async double-buffered. Smem row stride 40 bf16 (80 B) -> conflict-free
// ldmatrix (80/4=20 banks/row; 8 rows hit distinct banks).
// ---------------------------------------------------------------------------
#define GM_STEPS (HID / 32)          // 32
#define GM_TPAD  80                  // bytes per smem row (40 bf16)
#define GM_TILE  (128 * GM_TPAD)     // 10240 B per operand tile
#define GM_BUF   (4 * GM_TILE)       // Ah,Al,Bh,Bl = 40960 B
#define GM_SMEM  (2 * GM_BUF)        // 81920 B

__global__ __launch_bounds__(256, 1) void gemm_mma(
    const __nv_bfloat16* __restrict__ Ah, const __nv_bfloat16* __restrict__ Al,
    const __nv_bfloat16* __restrict__ Bh, const __nv_bfloat16* __restrict__ Bl,
    const float* __restrict__ bias, float* __restrict__ C, int M, int N)
{
    extern __shared__ __align__(128) char sm[];
    const uint32_t smb = smem_u32(sm);
    const int tid = threadIdx.x;
    const int lane = tid & 31, w = tid >> 5;
    const int wr = w >> 2;   // 0..1  -> 64-row band
    const int wc = w & 3;    // 0..3  -> 32-col band
    const int m0 = blockIdx.y * 128, n0 = blockIdx.x * 128;
    const int K = HID;

    const __nv_bfloat16* gb[4] = {
        Ah + (size_t)m0 * K, Al + (size_t)m0 * K,
        Bh + (size_t)n0 * K, Bl + (size_t)n0 * K };

    // load one k-step (4 tiles of 128x32 bf16) into buffer b
    auto load_step = [&](int b, int k0) {
        uint32_t bufb = smb + b * GM_BUF;
        #pragma unroll
        for (int j = 0; j < 8; j++) {
            int i = tid + j * 256;              // 0..2047
            int t = i >> 9;                     // tile 0..3
            int r = (i >> 2) & 127;             // row
            int c = i & 3;                      // 16B chunk
            const __nv_bfloat16* src = gb[t] + (size_t)r * K + k0 + c * 8;
            uint32_t dst = bufb + t * GM_TILE + r * GM_TPAD + c * 16;
            CP_ASYNC16(dst, src);
        }
    };

    float acc[4][4][4];   // [mi][nt][reg]
    #pragma unroll
    for (int mi = 0; mi < 4; mi++)
        #pragma unroll
        for (int nt = 0; nt < 4; nt++)
            #pragma unroll
            for (int r = 0; r < 4; r++) acc[mi][nt][r] = 0.f;

    // per-lane ldmatrix source addresses (byte offsets within a tile)
    const uint32_t a_off = (uint32_t)(wr * 64 + (lane & 15)) * GM_TPAD + (lane >> 4) * 16;
    const int q = lane >> 3;   // B: 4 matrices per x4
    const uint32_t b_off = (uint32_t)(wc * 32 + (q >> 1) * 8 + (lane & 7)) * GM_TPAD
                         + (q & 1) * 16;

    load_step(0, 0);
    CP_COMMIT();

    for (int t = 0; t < GM_STEPS; t++) {
        if (t + 1 < GM_STEPS) {
            load_step((t + 1) & 1, (t + 1) * 32);
            CP_COMMIT();
            CP_WAIT(1);
        } else {
            CP_WAIT(0);
        }
        __syncthreads();

        const uint32_t bb = smb + (t & 1) * GM_BUF;
        #pragma unroll
        for (int kk = 0; kk < 2; kk++) {
            const uint32_t kb = kk * 32;   // 16 bf16 = 32 B
            uint32_t af[4][4], bh[4][2], bl[4][2];

            // B hi/lo fragments: 2 x4-ldmatrix each cover 2 n8-tiles
            #pragma unroll
            for (int p = 0; p < 2; p++) {
                uint32_t rb = bb + 2 * GM_TILE + b_off + p * 16 * GM_TPAD + kb;
                uint32_t tmp[4];
                LDM4(tmp, rb);
                bh[2 * p][0] = tmp[0]; bh[2 * p][1] = tmp[1];
                bh[2 * p + 1][0] = tmp[2]; bh[2 * p + 1][1] = tmp[3];
                LDM4(tmp, rb + GM_TILE);
                bl[2 * p][0] = tmp[0]; bl[2 * p][1] = tmp[1];
                bl[2 * p + 1][0] = tmp[2]; bl[2 * p + 1][1] = tmp[3];
            }

            // Ah fragments -> mma with Bh and Bl
            #pragma unroll
            for (int mi = 0; mi < 4; mi++) {
                LDM4(af[mi], bb + a_off + (uint32_t)mi * 16 * GM_TPAD + kb);
            }
            #pragma unroll
            for (int mi = 0; mi < 4; mi++)
                #pragma unroll
                for (int nt = 0; nt < 4; nt++) {
                    MMA16816(acc[mi][nt], af[mi], bh[nt]);
                    MMA16816(acc[mi][nt], af[mi], bl[nt]);
                }

            // Al fragments -> mma with Bh
            #pragma unroll
            for (int mi = 0; mi < 4; mi++) {
                LDM4(af[mi], bb + GM_TILE + a_off + (uint32_t)mi * 16 * GM_TPAD + kb);
            }
            #pragma unroll
            for (int mi = 0; mi < 4; mi++)
                #pragma unroll
                for (int nt = 0; nt < 4; nt++)
                    MMA16816(acc[mi][nt], af[mi], bh[nt]);
        }
        __syncthreads();
    }

    // epilogue
    const int rbase = m0 + wr * 64 + (lane >> 2);
    #pragma unroll
    for (int nt = 0; nt < 4; nt++) {
        const int col = n0 + wc * 32 + nt * 8 + (lane & 3) * 2;
        const float2 bv = *(const float2*)&bias[col];
        #pragma unroll
        for (int mi = 0; mi < 4; mi++) {
            int r0 = rbase + mi * 16;
            *(float2*)&C[(size_t)r0 * N + col] =
                make_float2(acc[mi][nt][0] + bv.x, acc[mi][nt][1] + bv.y);
            *(float2*)&C[(size_t)(r0 + 8) * N + col] =
                make_float2(acc[mi][nt][2] + bv.x, acc[mi][nt][3] + bv.y);
        }
    }
}

// ---------------------------------------------------------------------------
// Fused causal attention, recompute variant. Per (bh, 64-row tile):
//  phase 1: S = 8*QK^T per tile, online (m,l) stats only (no gmem writes)
//  phase 2: recompute S, write normalized probs once, accumulate ctx += P V
// ---------------------------------------------------------------------------
#define SD 68
#define ATTN_SMEM (3 * 64 * SD * 4)   // Qs, Ks, Vs = 52224 B

__global__ __launch_bounds__(256, 3) void attn_fused(
    const float* __restrict__ q, const float* __restrict__ k,
    const float* __restrict__ v, float* __restrict__ attn,
    float* __restrict__ ctx)
{
    extern __shared__ float smf[];
    float (*Qs)[SD] = (float(*)[SD])smf;             // [d][i] Q^T (persistent)
    float (*Ks)[SD] = (float(*)[SD])(smf + 64 * SD); // [d][j] K^T / later [j][i] P^T
    float (*Vs)[SD] = (float(*)[SD])(smf + 128 * SD);// [j][d] V

    const int tid = threadIdx.x;
    const int tx = tid & 15, ty = tid >> 4;
    const int mt = gridDim.x - 1 - blockIdx.x;  // heavy tiles first
    const int bh = blockIdx.y;
    const int b = bh >> 4, h = bh & 15;
    const int m0 = mt * 64;

    const float* Q  = q + (size_t)b * SEQ * HID + h * HD;
    const float* Kp = k + (size_t)b * SEQ * HID + h * HD;
    const float* Vp = v + (size_t)b * SEQ * HID + h * HD;
    float* arow = attn + (size_t)bh * SEQ * SEQ;

    // load Q tile transposed: Qs[d][i]
    for (int it = tid; it < 64 * 16; it += 256) {
        int r = it >> 4;
        int c = (it & 15) << 2;
        float4 vq = *(const float4*)&Q[(size_t)(m0 + r) * HID + c];
        Qs[c + 0][r] = vq.x; Qs[c + 1][r] = vq.y;
        Qs[c + 2][r] = vq.z; Qs[c + 3][r] = vq.w;
    }

    float m_[4] = {-INFINITY, -INFINITY, -INFINITY, -INFINITY};
    float l_[4] = {0.f, 0.f, 0.f, 0.f};

    // ---------------- phase 1: stats only ----------------
    for (int jt = 0; jt <= mt; jt++) {
        for (int it = tid; it < 64 * 16; it += 256) {
            int r = it >> 4;
            int c = (it & 15) << 2;
            float4 kv = *(const float4*)&Kp[(size_t)(jt * 64 + r) * HID + c];
            Ks[c + 0][r] = kv.x; Ks[c + 1][r] = kv.y;
            Ks[c + 2][r] = kv.z; Ks[c + 3][r] = kv.w;
        }
        __syncthreads();

        ull sacc[4][2];
        #pragma unroll
        for (int i = 0; i < 4; i++) { sacc[i][0] = 0ull; sacc[i][1] = 0ull; }

        #pragma unroll
        for (int d = 0; d < 64; d++) {
            float4 qa = *(float4*)&Qs[d][ty * 4];
            float4 kb = *(float4*)&Ks[d][tx * 4];
            ull b01 = pk2(kb.x, kb.y), b23 = pk2(kb.z, kb.w);
            float qv[4] = {qa.x, qa.y, qa.z, qa.w};
            #pragma unroll
            for (int i = 0; i < 4; i++) {
                ull ad = dup2(qv[i]);
                ffma2(sacc[i][0], ad, b01);
                ffma2(sacc[i][1], ad, b23);
            }
        }

        const int gj0 = jt * 64 + tx * 4;
        #pragma unroll
        for (int ii = 0; ii < 4; ii++) {
            float2 p0 = unp2(sacc[ii][0]);
            float2 p1 = unp2(sacc[ii][1]);
            const int gi = m0 + ty * 4 + ii;
            float t0 = (gj0 + 0 > gi) ? -INFINITY : p0.x * 8.0f;
            float t1 = (gj0 + 1 > gi) ? -INFINITY : p0.y * 8.0f;
            float t2 = (gj0 + 2 > gi) ? -INFINITY : p1.x * 8.0f;
            float t3 = (gj0 + 3 > gi) ? -INFINITY : p1.y * 8.0f;

            float tm = fmaxf(fmaxf(t0, t1), fmaxf(t2, t3));
            #pragma unroll
            for (int o = 1; o < 16; o <<= 1)
                tm = fmaxf(tm, __shfl_xor_sync(0xffffffffu, tm, o));
            float mnew = fmaxf(m_[ii], tm);

            float es = __expf(t0 - mnew) + __expf(t1 - mnew) +
                       __expf(t2 - mnew) + __expf(t3 - mnew);
            #pragma unroll
            for (int o = 1; o < 16; o <<= 1)
                es += __shfl_xor_sync(0xffffffffu, es, o);

            l_[ii] = l_[ii] * __expf(m_[ii] - mnew) + es;
            m_[ii] = mnew;
        }
        __syncthreads();
    }

    float invl[4];
    #pragma unroll
    for (int ii = 0; ii < 4; ii++) invl[ii] = 1.0f / l_[ii];

    // ---------------- phase 2: recompute, write P, accumulate ctx ----------
    ull cacc[4][2];
    #pragma unroll
    for (int i = 0; i < 4; i++) { cacc[i][0] = 0ull; cacc[i][1] = 0ull; }

    for (int jt = 0; jt <= mt; jt++) {
        for (int it = tid; it < 64 * 16; it += 256) {
            int r = it >> 4;
            int c = (it & 15) << 2;
            float4 kv = *(const float4*)&Kp[(size_t)(jt * 64 + r) * HID + c];
            Ks[c + 0][r] = kv.x; Ks[c + 1][r] = kv.y;
            Ks[c + 2][r] = kv.z; Ks[c + 3][r] = kv.w;
            *(float4*)&Vs[r][c] = *(const float4*)&Vp[(size_t)(jt * 64 + r) * HID + c];
        }
        __syncthreads();

        ull sacc[4][2];
        #pragma unroll
        for (int i = 0; i < 4; i++) { sacc[i][0] = 0ull; sacc[i][1] = 0ull; }
        #pragma unroll
        for (int d = 0; d < 64; d++) {
            float4 qa = *(float4*)&Qs[d][ty * 4];
            float4 kb = *(float4*)&Ks[d][tx * 4];
            ull b01 = pk2(kb.x, kb.y), b23 = pk2(kb.z, kb.w);
            float qv[4] = {qa.x, qa.y, qa.z, qa.w};
            #pragma unroll
            for (int i = 0; i < 4; i++) {
                ull ad = dup2(qv[i]);
                ffma2(sacc[i][0], ad, b01);
                ffma2(sacc[i][1], ad, b23);
            }
        }
        __syncthreads();   // everyone done reading Ks before P^T overwrite

        const int gj0 = jt * 64 + tx * 4;
        #pragma unroll
        for (int ii = 0; ii < 4; ii++) {
            const int gi = m0 + ty * 4 + ii;
            float2 p0 = unp2(sacc[ii][0]);
            float2 p1 = unp2(sacc[ii][1]);
            float q0 = (gj0 + 0 > gi) ? 0.f : __expf(p0.x * 8.0f - m_[ii]) * invl[ii];
            float q1 = (gj0 + 1 > gi) ? 0.f : __expf(p0.y * 8.0f - m_[ii]) * invl[ii];
            float q2 = (gj0 + 2 > gi) ? 0.f : __expf(p1.x * 8.0f - m_[ii]) * invl[ii];
            float q3 = (gj0 + 3 > gi) ? 0.f : __expf(p1.y * 8.0f - m_[ii]) * invl[ii];
            *(float4*)&arow[(size_t)gi * SEQ + gj0] = make_float4(q0, q1, q2, q3);
            // stage P^T into Ks
            Ks[tx * 4 + 0][ty * 4 + ii] = q0;
            Ks[tx * 4 + 1][ty * 4 + ii] = q1;
            Ks[tx * 4 + 2][ty * 4 + ii] = q2;
            Ks[tx * 4 + 3][ty * 4 + ii] = q3;
        }
        __syncthreads();

        #pragma unroll
        for (int j = 0; j < 64; j++) {
            float4 pv = *(float4*)&Ks[j][ty * 4];
            float4 vv = *(float4*)&Vs[j][tx * 4];
            ull v01 = pk2(vv.x, vv.y), v23 = pk2(vv.z, vv.w);
            float pvv[4] = {pv.x, pv.y, pv.z, pv.w};
            #pragma unroll
            for (int i = 0; i < 4; i++) {
                ull ad = dup2(pvv[i]);
                ffma2(cacc[i][0], ad, v01);
                ffma2(cacc[i][1], ad, v23);
            }
        }
        __syncthreads();
    }

    // write ctx
    #pragma unroll
    for (int ii = 0; ii < 4; ii++) {
        int gi = m0 + ty * 4 + ii;
        float2 c0 = unp2(cacc[ii][0]);
        float2 c1 = unp2(cacc[ii][1]);
        *(float4*)&ctx[((size_t)b * SEQ + gi) * HID + h * HD + tx * 4] =
            make_float4(c0.x, c0.y, c1.x, c1.y);
    }

    // zero-fill masked columns
    const int zstart = (mt + 1) * 64;
    const int zcols = SEQ - zstart;
    if (zcols > 0) {
        const int nv = zcols >> 2;
        for (int it = tid; it < 64 * nv; it += 256) {
            int r = it / nv, c = it % nv;
            *(float4*)&arow[(size_t)(m0 + r) * SEQ + zstart + c * 4] =
                make_float4(0.f, 0.f, 0.f, 0.f);
        }
    }
}

// ---------------------------------------------------------------------------
extern "C" void kernel_launch(void* const* d_in, const int* in_sizes, int n_in,
                              void* d_out, int out_size)
{
    const float* x  = (const float*)d_in[0];
    const float* Wq = (const float*)d_in[1];
    const float* bq = (const float*)d_in[2];
    const float* Wk = (const float*)d_in[3];
    const float* bk = (const float*)d_in[4];
    const float* Wv = (const float*)d_in[5];
    const float* bv = (const float*)d_in[6];
    const float* Wo = (const float*)d_in[7];
    const float* bo = (const float*)d_in[8];

    float* out = (float*)d_out;

    void *pq, *pk, *pv, *pctx, *pattn, *pah, *pal, *pwh, *pwl;
    cudaGetSymbolAddress(&pq, g_q);
    cudaGetSymbolAddress(&pk, g_k);
    cudaGetSymbolAddress(&pv, g_v);
    cudaGetSymbolAddress(&pctx, g_ctx);
    cudaGetSymbolAddress(&pattn, g_attn_scratch);
    cudaGetSymbolAddress(&pah, g_ah);
    cudaGetSymbolAddress(&pal, g_al);
    cudaGetSymbolAddress(&pwh, g_wh);
    cudaGetSymbolAddress(&pwl, g_wl);

    __nv_bfloat16* ah = (__nv_bfloat16*)pah;
    __nv_bfloat16* al = (__nv_bfloat16*)pal;
    __nv_bfloat16* wh = (__nv_bfloat16*)pwh;
    __nv_bfloat16* wl = (__nv_bfloat16*)pwl;

    float* attn = ((size_t)out_size >= OUT_ELEMS + ATTN_ELEMS)
                      ? out + OUT_ELEMS
                      : (float*)pattn;

    cudaFuncSetAttribute(gemm_mma, cudaFuncAttributeMaxDynamicSharedMemorySize, GM_SMEM);
    cudaFuncSetAttribute(attn_fused, cudaFuncAttributeMaxDynamicSharedMemorySize, ATTN_SMEM);

    const int NW = HID * HID;    // 1,048,576
    const int NX = MROWS * HID;  // 4,194,304

    // splits
    conv_split<<<NX / 1024, 256>>>(x, ah, al, NX);
    conv_split<<<NW / 1024, 256>>>(Wq, wh + 0 * (size_t)NW, wl + 0 * (size_t)NW, NW);
    conv_split<<<NW / 1024, 256>>>(Wk, wh + 1 * (size_t)NW, wl + 1 * (size_t)NW, NW);
    conv_split<<<NW / 1024, 256>>>(Wv, wh + 2 * (size_t)NW, wl + 2 * (size_t)NW, NW);
    conv_split<<<NW / 1024, 256>>>(Wo, wh + 3 * (size_t)NW, wl + 3 * (size_t)NW, NW);

    dim3 gG(HID / 128, MROWS / 128);  // (8, 32)
    gemm_mma<<<gG, 256, GM_SMEM>>>(ah, al, wh + 0 * (size_t)NW, wl + 0 * (size_t)NW,
                                   bq, (float*)pq, MROWS, HID);
    gemm_mma<<<gG, 256, GM_SMEM>>>(ah, al, wh + 1 * (size_t)NW, wl + 1 * (size_t)NW,
                                   bk, (float*)pk, MROWS, HID);
    gemm_mma<<<gG, 256, GM_SMEM>>>(ah, al, wh + 2 * (size_t)NW, wl + 2 * (size_t)NW,
                                   bv, (float*)pv, MROWS, HID);

    dim3 gAttn(SEQ / 64, BATCH * NH);  // (32, 32)
    attn_fused<<<gAttn, 256, ATTN_SMEM>>>((const float*)pq, (const float*)pk,
                                          (const float*)pv, attn, (float*)pctx);

    conv_split<<<NX / 1024, 256>>>((const float*)pctx, ah, al, NX);
    gemm_mma<<<gG, 256, GM_SMEM>>>(ah, al, wh + 3 * (size_t)NW, wl + 3 * (size_t)NW,
                                   bo, out, MROWS, HID);
}

// round 12
// speedup vs baseline: 2.9417x; 2.9417x over previous
#include <cuda_runtime.h>
#include <cuda_bf16.h>
#include <cstdint>
#include <math.h>

// Problem constants
#define BATCH 2
#define SEQ   2048
#define HID   1024
#define NH    16
#define HD    64
#define MROWS (BATCH * SEQ)   // 4096

static const size_t OUT_ELEMS  = (size_t)BATCH * SEQ * HID;              // 4,194,304
static const size_t ATTN_ELEMS = (size_t)BATCH * NH * SEQ * (size_t)SEQ; // 134,217,728

// Scratch (allocation-free: __device__ globals)
__device__ __align__(16) float g_q[MROWS * HID];
__device__ __align__(16) float g_k[MROWS * HID];
__device__ __align__(16) float g_v[MROWS * HID];
__device__ __align__(16) float g_ctx[MROWS * HID];
__device__ __align__(16) float g_attn_scratch[(size_t)BATCH * NH * SEQ * (size_t)SEQ];

// bf16 hi/lo splits
__device__ __align__(16) __nv_bfloat16 g_ah[MROWS * HID];   // activations hi
__device__ __align__(16) __nv_bfloat16 g_al[MROWS * HID];   // activations lo
__device__ __align__(16) __nv_bfloat16 g_wh[4 * HID * HID]; // weights hi (q,k,v,o)
__device__ __align__(16) __nv_bfloat16 g_wl[4 * HID * HID]; // weights lo
__device__ __align__(16) __nv_bfloat16 g_qh[MROWS * HID];
__device__ __align__(16) __nv_bfloat16 g_ql[MROWS * HID];
__device__ __align__(16) __nv_bfloat16 g_kh[MROWS * HID];
__device__ __align__(16) __nv_bfloat16 g_kl[MROWS * HID];
__device__ __align__(16) __nv_bfloat16 g_vh[MROWS * HID];
__device__ __align__(16) __nv_bfloat16 g_vl[MROWS * HID];

// ---------------------------------------------------------------------------
// PTX helpers (sm_80-baseline features only)
// ---------------------------------------------------------------------------
__device__ __forceinline__ uint32_t smem_u32(const void* p) {
    uint32_t a;
    asm("{ .reg .u64 t; cvta.to.shared.u64 t, %1; cvt.u32.u64 %0, t; }" : "=r"(a) : "l"(p));
    return a;
}

#define CP_ASYNC16(dst, src) \
    asm volatile("cp.async.cg.shared.global [%0], [%1], 16;" :: "r"(dst), "l"(src) : "memory")
#define CP_COMMIT() asm volatile("cp.async.commit_group;" ::: "memory")
#define CP_WAIT(N)  asm volatile("cp.async.wait_group %0;" :: "n"(N) : "memory")

#define LDM4(r, a)                                                              \
    asm volatile("ldmatrix.sync.aligned.m8n8.x4.shared.b16 {%0,%1,%2,%3}, [%4];" \
                 : "=r"((r)[0]), "=r"((r)[1]), "=r"((r)[2]), "=r"((r)[3]) : "r"(a))

#define LDM4T(r, a)                                                                   \
    asm volatile("ldmatrix.sync.aligned.m8n8.x4.trans.shared.b16 {%0,%1,%2,%3}, [%4];" \
                 : "=r"((r)[0]), "=r"((r)[1]), "=r"((r)[2]), "=r"((r)[3]) : "r"(a))

#define MMA16816(c, a, b0, b1)                                                  \
    asm volatile("mma.sync.aligned.m16n8k16.row.col.f32.bf16.bf16.f32 "         \
                 "{%0,%1,%2,%3}, {%4,%5,%6,%7}, {%8,%9}, {%0,%1,%2,%3};"        \
                 : "+f"((c)[0]), "+f"((c)[1]), "+f"((c)[2]), "+f"((c)[3])       \
                 : "r"((a)[0]), "r"((a)[1]), "r"((a)[2]), "r"((a)[3]),          \
                   "r"(b0), "r"(b1))

__device__ __forceinline__ float ex2f(float x) {
    float r; asm("ex2.approx.f32 %0, %1;" : "=f"(r) : "f"(x)); return r;
}
__device__ __forceinline__ void split2(float x, float y, uint32_t& hi, uint32_t& lo) {
    __nv_bfloat16 hx = __float2bfloat16(x), hy = __float2bfloat16(y);
    __nv_bfloat162 hp(hx, hy);
    hi = *(uint32_t*)&hp;
    __nv_bfloat162 lp = __floats2bfloat162_rn(x - __bfloat162float(hx),
                                              y - __bfloat162float(hy));
    lo = *(uint32_t*)&lp;
}

// ---------------------------------------------------------------------------
// fp32 -> bf16 hi/lo split
// ---------------------------------------------------------------------------
__global__ __launch_bounds__(256) void conv_split(
    const float* __restrict__ src, __nv_bfloat16* __restrict__ hi,
    __nv_bfloat16* __restrict__ lo, int n)
{
    int i = (blockIdx.x * 256 + threadIdx.x) * 4;
    if (i >= n) return;
    float4 v = *(const float4*)&src[i];
    __nv_bfloat16 h0 = __float2bfloat16(v.x), h1 = __float2bfloat16(v.y);
    __nv_bfloat16 h2 = __float2bfloat16(v.z), h3 = __float2bfloat16(v.w);
    __nv_bfloat16 l0 = __float2bfloat16(v.x - __bfloat162float(h0));
    __nv_bfloat16 l1 = __float2bfloat16(v.y - __bfloat162float(h1));
    __nv_bfloat16 l2 = __float2bfloat16(v.z - __bfloat162float(h2));
    __nv_bfloat16 l3 = __float2bfloat16(v.w - __bfloat162float(h3));
    *(__nv_bfloat162*)&hi[i]     = __nv_bfloat162(h0, h1);
    *(__nv_bfloat162*)&hi[i + 2] = __nv_bfloat162(h2, h3);
    *(__nv_bfloat162*)&lo[i]     = __nv_bfloat162(l0, l1);
    *(__nv_bfloat162*)&lo[i + 2] = __nv_bfloat162(l2, l3);
}

// ---------------------------------------------------------------------------
// Tensor-core (mma.sync bf16) 3-split GEMM (proven in R6):
//   C[M,N] = Ah@Bh^T + Ah@Bl^T + Al@Bh^T + bias
// ---------------------------------------------------------------------------
#define GM_STEPS (HID / 32)
#define GM_TPAD  80
#define GM_TILE  (128 * GM_TPAD)
#define GM_BUF   (4 * GM_TILE)
#define GM_SMEM  (2 * GM_BUF)

__global__ __launch_bounds__(256, 1) void gemm_mma(
    const __nv_bfloat16* __restrict__ Ah, const __nv_bfloat16* __restrict__ Al,
    const __nv_bfloat16* __restrict__ Bh, const __nv_bfloat16* __restrict__ Bl,
    const float* __restrict__ bias, float* __restrict__ C, int M, int N)
{
    extern __shared__ __align__(128) char sm[];
    const uint32_t smb = smem_u32(sm);
    const int tid = threadIdx.x;
    const int lane = tid & 31, w = tid >> 5;
    const int wr = w >> 2;
    const int wc = w & 3;
    const int m0 = blockIdx.y * 128, n0 = blockIdx.x * 128;
    const int K = HID;

    const __nv_bfloat16* gb[4] = {
        Ah + (size_t)m0 * K, Al + (size_t)m0 * K,
        Bh + (size_t)n0 * K, Bl + (size_t)n0 * K };

    auto load_step = [&](int b, int k0) {
        uint32_t bufb = smb + b * GM_BUF;
        #pragma unroll
        for (int j = 0; j < 8; j++) {
            int i = tid + j * 256;
            int t = i >> 9;
            int r = (i >> 2) & 127;
            int c = i & 3;
            const __nv_bfloat16* src = gb[t] + (size_t)r * K + k0 + c * 8;
            uint32_t dst = bufb + t * GM_TILE + r * GM_TPAD + c * 16;
            CP_ASYNC16(dst, src);
        }
    };

    float acc[4][4][4];
    #pragma unroll
    for (int mi = 0; mi < 4; mi++)
        #pragma unroll
        for (int nt = 0; nt < 4; nt++)
            #pragma unroll
            for (int r = 0; r < 4; r++) acc[mi][nt][r] = 0.f;

    const uint32_t a_off = (uint32_t)(wr * 64 + (lane & 15)) * GM_TPAD + (lane >> 4) * 16;
    const int q = lane >> 3;
    const uint32_t b_off = (uint32_t)(wc * 32 + (q >> 1) * 8 + (lane & 7)) * GM_TPAD
                         + (q & 1) * 16;

    load_step(0, 0);
    CP_COMMIT();

    for (int t = 0; t < GM_STEPS; t++) {
        if (t + 1 < GM_STEPS) {
            load_step((t + 1) & 1, (t + 1) * 32);
            CP_COMMIT();
            CP_WAIT(1);
        } else {
            CP_WAIT(0);
        }
        __syncthreads();

        const uint32_t bb = smb + (t & 1) * GM_BUF;
        #pragma unroll
        for (int kk = 0; kk < 2; kk++) {
            const uint32_t kb = kk * 32;
            uint32_t af[4][4], bh[4][2], bl[4][2];

            #pragma unroll
            for (int p = 0; p < 2; p++) {
                uint32_t rb = bb + 2 * GM_TILE + b_off + p * 16 * GM_TPAD + kb;
                uint32_t tmp[4];
                LDM4(tmp, rb);
                bh[2 * p][0] = tmp[0]; bh[2 * p][1] = tmp[1];
                bh[2 * p + 1][0] = tmp[2]; bh[2 * p + 1][1] = tmp[3];
                LDM4(tmp, rb + GM_TILE);
                bl[2 * p][0] = tmp[0]; bl[2 * p][1] = tmp[1];
                bl[2 * p + 1][0] = tmp[2]; bl[2 * p + 1][1] = tmp[3];
            }

            #pragma unroll
            for (int mi = 0; mi < 4; mi++) {
                LDM4(af[mi], bb + a_off + (uint32_t)mi * 16 * GM_TPAD + kb);
            }
            #pragma unroll
            for (int mi = 0; mi < 4; mi++)
                #pragma unroll
                for (int nt = 0; nt < 4; nt++) {
                    MMA16816(acc[mi][nt], af[mi], bh[nt][0], bh[nt][1]);
                    MMA16816(acc[mi][nt], af[mi], bl[nt][0], bl[nt][1]);
                }

            #pragma unroll
            for (int mi = 0; mi < 4; mi++) {
                LDM4(af[mi], bb + GM_TILE + a_off + (uint32_t)mi * 16 * GM_TPAD + kb);
            }
            #pragma unroll
            for (int mi = 0; mi < 4; mi++)
                #pragma unroll
                for (int nt = 0; nt < 4; nt++)
                    MMA16816(acc[mi][nt], af[mi], bh[nt][0], bh[nt][1]);
        }
        __syncthreads();
    }

    const int rbase = m0 + wr * 64 + (lane >> 2);
    #pragma unroll
    for (int nt = 0; nt < 4; nt++) {
        const int col = n0 + wc * 32 + nt * 8 + (lane & 3) * 2;
        const float2 bv = *(const float2*)&bias[col];
        #pragma unroll
        for (int mi = 0; mi < 4; mi++) {
            int r0 = rbase + mi * 16;
            *(float2*)&C[(size_t)r0 * N + col] =
                make_float2(acc[mi][nt][0] + bv.x, acc[mi][nt][1] + bv.y);
            *(float2*)&C[(size_t)(r0 + 8) * N + col] =
                make_float2(acc[mi][nt][2] + bv.x, acc[mi][nt][3] + bv.y);
        }
    }
}

// ---------------------------------------------------------------------------
// Tensor-core causal flash attention (mma.sync, bf16 3-split).
// CTA: 256 threads = 8 warps; Q row tile 128 (warp = 16 rows); j-tile 64.
// Phase 1: S = QK^T (3-term), online (m, l) stats only.
// Phase 2: recompute S, p = exp2(s*C - m)/l, write P, ctx += P@V (3-term).
// ---------------------------------------------------------------------------
#define AT_STRIDE 144                    // bytes per smem row (64 bf16 + pad)
#define AT_QTILE  (128 * AT_STRIDE)      // 18432
#define AT_Q      (2 * AT_QTILE)         // Qh + Ql = 36864
#define AT_KVT    (64 * AT_STRIDE)       // 9216
#define AT_KVBUF  (4 * AT_KVT)           // Kh,Kl,Vh,Vl = 36864
#define AT_SMEM   (AT_Q + 2 * AT_KVBUF)  // 110592
#define C_SCALE   11.5415603270f         // 8 * log2(e)

__global__ __launch_bounds__(256) void attn_mma(
    const __nv_bfloat16* __restrict__ qh, const __nv_bfloat16* __restrict__ ql,
    const __nv_bfloat16* __restrict__ kh, const __nv_bfloat16* __restrict__ kl,
    const __nv_bfloat16* __restrict__ vh, const __nv_bfloat16* __restrict__ vl,
    float* __restrict__ attn, float* __restrict__ ctx)
{
    extern __shared__ __align__(1024) char smc[];
    const uint32_t smb = smem_u32(smc);
    const int tid = threadIdx.x, lane = tid & 31, w = tid >> 5;
    const int mt = (int)gridDim.x - 1 - (int)blockIdx.x;   // heavy-first
    const int bh = blockIdx.y, b = bh >> 4, h = bh & 15;
    const int m0 = mt * 128;
    const int njt = 2 * mt + 2;
    const size_t hoff = (size_t)b * SEQ * HID + h * 64;
    const __nv_bfloat16* src[6] = { qh + hoff, ql + hoff, kh + hoff,
                                    kl + hoff, vh + hoff, vl + hoff };
    float* arow = attn + (size_t)bh * SEQ * SEQ;

    // Q tiles: Qh at 0, Ql at AT_QTILE (128 rows x 8 chunks x 2 tiles)
    for (int i = tid; i < 2048; i += 256) {
        int t = i >> 10, r = (i >> 3) & 127, c = i & 7;
        CP_ASYNC16(smb + t * AT_QTILE + r * AT_STRIDE + c * 16,
                   src[t] + (size_t)(m0 + r) * HID + c * 8);
    }
    CP_COMMIT();

    auto load_kv = [&](int buf, int jt, int ntiles) {
        uint32_t base = smb + AT_Q + buf * AT_KVBUF;
        int j0 = jt * 64;
        for (int i = tid; i < ntiles * 512; i += 256) {
            int t = i >> 9, r = (i >> 3) & 63, c = i & 7;
            CP_ASYNC16(base + t * AT_KVT + r * AT_STRIDE + c * 16,
                       src[2 + t] + (size_t)(j0 + r) * HID + c * 8);
        }
    };

    const int wq = w * 16;
    const uint32_t qa  = smb + (uint32_t)(wq + (lane & 15)) * AT_STRIDE + (lane >> 4) * 16;
    const int q2 = lane >> 3;
    const uint32_t kfo = (uint32_t)((q2 >> 1) * 8 + (lane & 7)) * AT_STRIDE + (q2 & 1) * 16;
    const int rbase = m0 + wq + (lane >> 2);

    uint32_t qhf[4][4];
    bool qloaded = false;

    // 3-term S compute into sacc
    auto compute_S = [&](uint32_t kb, float (*sacc)[4]) {
        #pragma unroll
        for (int nt = 0; nt < 8; nt++)
            #pragma unroll
            for (int r = 0; r < 4; r++) sacc[nt][r] = 0.f;
        #pragma unroll
        for (int kt = 0; kt < 4; kt++) {
            uint32_t qlf[4];
            LDM4(qlf, qa + AT_QTILE + kt * 32);
            #pragma unroll
            for (int p = 0; p < 4; p++) {
                uint32_t kh4[4], kl4[4];
                uint32_t ka = kb + kfo + (uint32_t)p * 16 * AT_STRIDE + kt * 32;
                LDM4(kh4, ka);
                LDM4(kl4, ka + AT_KVT);
                MMA16816(sacc[2 * p],     qhf[kt], kh4[0], kh4[1]);
                MMA16816(sacc[2 * p + 1], qhf[kt], kh4[2], kh4[3]);
                MMA16816(sacc[2 * p],     qhf[kt], kl4[0], kl4[1]);
                MMA16816(sacc[2 * p + 1], qhf[kt], kl4[2], kl4[3]);
                MMA16816(sacc[2 * p],     qlf, kh4[0], kh4[1]);
                MMA16816(sacc[2 * p + 1], qlf, kh4[2], kh4[3]);
            }
        }
    };

    float m_[2] = { -1e30f, -1e30f };
    float l_[2] = { 0.f, 0.f };

    // ---------------- phase 1: stats ----------------
    load_kv(0, 0, 2);
    CP_COMMIT();
    for (int jt = 0; jt < njt; jt++) {
        if (jt + 1 < njt) { load_kv((jt + 1) & 1, jt + 1, 2); CP_COMMIT(); CP_WAIT(1); }
        else              { CP_WAIT(0); }
        __syncthreads();
        if (!qloaded) {
            qloaded = true;
            #pragma unroll
            for (int kt = 0; kt < 4; kt++) LDM4(qhf[kt], qa + kt * 32);
        }

        const uint32_t kb = smb + AT_Q + (jt & 1) * AT_KVBUF;
        float sacc[8][4];
        compute_S(kb, sacc);

        const int colb = jt * 64 + (lane & 3) * 2;
        #pragma unroll
        for (int hf = 0; hf < 2; hf++) {
            const int row = rbase + 8 * hf;
            float sv[16];
            float tmax = -1e30f;
            #pragma unroll
            for (int nt = 0; nt < 8; nt++) {
                int c0 = colb + nt * 8;
                float s0 = (c0     > row) ? -1e30f : sacc[nt][2 * hf]     * C_SCALE;
                float s1 = (c0 + 1 > row) ? -1e30f : sacc[nt][2 * hf + 1] * C_SCALE;
                sv[2 * nt] = s0; sv[2 * nt + 1] = s1;
                tmax = fmaxf(tmax, fmaxf(s0, s1));
            }
            tmax = fmaxf(tmax, __shfl_xor_sync(0xffffffffu, tmax, 1));
            tmax = fmaxf(tmax, __shfl_xor_sync(0xffffffffu, tmax, 2));
            float mnew = fmaxf(m_[hf], tmax);
            float s = 0.f;
            #pragma unroll
            for (int e = 0; e < 16; e++) s += ex2f(sv[e] - mnew);
            s += __shfl_xor_sync(0xffffffffu, s, 1);
            s += __shfl_xor_sync(0xffffffffu, s, 2);
            l_[hf] = l_[hf] * ex2f(m_[hf] - mnew) + s;
            m_[hf] = mnew;
        }
        __syncthreads();
    }

    const float invl[2] = { 1.f / l_[0], 1.f / l_[1] };

    // ---------------- phase 2: P + PV ----------------
    float cacc[8][4];
    #pragma unroll
    for (int nt = 0; nt < 8; nt++)
        #pragma unroll
        for (int r = 0; r < 4; r++) cacc[nt][r] = 0.f;

    load_kv(0, 0, 4);
    CP_COMMIT();
    for (int jt = 0; jt < njt; jt++) {
        if (jt + 1 < njt) { load_kv((jt + 1) & 1, jt + 1, 4); CP_COMMIT(); CP_WAIT(1); }
        else              { CP_WAIT(0); }
        __syncthreads();

        const uint32_t kb = smb + AT_Q + (jt & 1) * AT_KVBUF;
        float sacc[8][4];
        compute_S(kb, sacc);

        const int colb = jt * 64 + (lane & 3) * 2;
        uint32_t aph[4][4], apl[4][4];
        #pragma unroll
        for (int nt = 0; nt < 8; nt++) {
            int c0 = colb + nt * 8;
            int kj = nt >> 1, sub = nt & 1;
            #pragma unroll
            for (int hf = 0; hf < 2; hf++) {
                const int row = rbase + 8 * hf;
                float p0 = (c0     > row) ? 0.f
                         : ex2f(fmaf(sacc[nt][2 * hf],     C_SCALE, -m_[hf])) * invl[hf];
                float p1 = (c0 + 1 > row) ? 0.f
                         : ex2f(fmaf(sacc[nt][2 * hf + 1], C_SCALE, -m_[hf])) * invl[hf];
                *(float2*)&arow[(size_t)row * SEQ + c0] = make_float2(p0, p1);
                split2(p0, p1, aph[kj][sub * 2 + hf], apl[kj][sub * 2 + hf]);
            }
        }

        const uint32_t vb = kb + 2 * AT_KVT;
        const uint32_t vfo = vb + (uint32_t)(lane & 15) * AT_STRIDE + (lane >> 4) * 16;
        #pragma unroll
        for (int kj = 0; kj < 4; kj++) {
            #pragma unroll
            for (int dp = 0; dp < 4; dp++) {
                uint32_t vh4[4], vl4[4];
                uint32_t va = vfo + (uint32_t)kj * 16 * AT_STRIDE + dp * 32;
                LDM4T(vh4, va);
                LDM4T(vl4, va + AT_KVT);
                MMA16816(cacc[2 * dp],     aph[kj], vh4[0], vh4[1]);
                MMA16816(cacc[2 * dp + 1], aph[kj], vh4[2], vh4[3]);
                MMA16816(cacc[2 * dp],     aph[kj], vl4[0], vl4[1]);
                MMA16816(cacc[2 * dp + 1], aph[kj], vl4[2], vl4[3]);
                MMA16816(cacc[2 * dp],     apl[kj], vh4[0], vh4[1]);
                MMA16816(cacc[2 * dp + 1], apl[kj], vh4[2], vh4[3]);
            }
        }
        __syncthreads();
    }

    // ctx write
    #pragma unroll
    for (int hf = 0; hf < 2; hf++) {
        const int row = rbase + 8 * hf;
        size_t off = ((size_t)b * SEQ + row) * HID + h * 64 + (lane & 3) * 2;
        #pragma unroll
        for (int nt = 0; nt < 8; nt++)
            *(float2*)&ctx[off + nt * 8] =
                make_float2(cacc[nt][2 * hf], cacc[nt][2 * hf + 1]);
    }

    // zero-fill fully masked columns
    const int zstart = m0 + 128;
    const int zc = SEQ - zstart;
    if (zc > 0) {
        const int nv = zc >> 2;
        for (int it = tid; it < 128 * nv; it += 256) {
            int r = it / nv, c = it - r * nv;
            *(float4*)&arow[(size_t)(m0 + r) * SEQ + zstart + c * 4] =
                make_float4(0.f, 0.f, 0.f, 0.f);
        }
    }
}

// ---------------------------------------------------------------------------
extern "C" void kernel_launch(void* const* d_in, const int* in_sizes, int n_in,
                              void* d_out, int out_size)
{
    const float* x  = (const float*)d_in[0];
    const float* Wq = (const float*)d_in[1];
    const float* bq = (const float*)d_in[2];
    const float* Wk = (const float*)d_in[3];
    const float* bk = (const float*)d_in[4];
    const float* Wv = (const float*)d_in[5];
    const float* bv = (const float*)d_in[6];
    const float* Wo = (const float*)d_in[7];
    const float* bo = (const float*)d_in[8];

    float* out = (float*)d_out;

    void *pq, *pk, *pv, *pctx, *pattn, *pah, *pal, *pwh, *pwl;
    void *pqh, *pql, *pkh, *pkl, *pvh, *pvl;
    cudaGetSymbolAddress(&pq, g_q);
    cudaGetSymbolAddress(&pk, g_k);
    cudaGetSymbolAddress(&pv, g_v);
    cudaGetSymbolAddress(&pctx, g_ctx);
    cudaGetSymbolAddress(&pattn, g_attn_scratch);
    cudaGetSymbolAddress(&pah, g_ah);
    cudaGetSymbolAddress(&pal, g_al);
    cudaGetSymbolAddress(&pwh, g_wh);
    cudaGetSymbolAddress(&pwl, g_wl);
    cudaGetSymbolAddress(&pqh, g_qh);
    cudaGetSymbolAddress(&pql, g_ql);
    cudaGetSymbolAddress(&pkh, g_kh);
    cudaGetSymbolAddress(&pkl, g_kl);
    cudaGetSymbolAddress(&pvh, g_vh);
    cudaGetSymbolAddress(&pvl, g_vl);

    __nv_bfloat16* ah = (__nv_bfloat16*)pah;
    __nv_bfloat16* al = (__nv_bfloat16*)pal;
    __nv_bfloat16* wh = (__nv_bfloat16*)pwh;
    __nv_bfloat16* wl = (__nv_bfloat16*)pwl;

    float* attn = ((size_t)out_size >= OUT_ELEMS + ATTN_ELEMS)
                      ? out + OUT_ELEMS
                      : (float*)pattn;

    cudaFuncSetAttribute(gemm_mma, cudaFuncAttributeMaxDynamicSharedMemorySize, GM_SMEM);
    cudaFuncSetAttribute(attn_mma, cudaFuncAttributeMaxDynamicSharedMemorySize, AT_SMEM);

    const int NW = HID * HID;    // 1,048,576
    const int NX = MROWS * HID;  // 4,194,304

    // input splits
    conv_split<<<NX / 1024, 256>>>(x, ah, al, NX);
    conv_split<<<NW / 1024, 256>>>(Wq, wh + 0 * (size_t)NW, wl + 0 * (size_t)NW, NW);
    conv_split<<<NW / 1024, 256>>>(Wk, wh + 1 * (size_t)NW, wl + 1 * (size_t)NW, NW);
    conv_split<<<NW / 1024, 256>>>(Wv, wh + 2 * (size_t)NW, wl + 2 * (size_t)NW, NW);
    conv_split<<<NW / 1024, 256>>>(Wo, wh + 3 * (size_t)NW, wl + 3 * (size_t)NW, NW);

    dim3 gG(HID / 128, MROWS / 128);  // (8, 32)
    gemm_mma<<<gG, 256, GM_SMEM>>>(ah, al, wh + 0 * (size_t)NW, wl + 0 * (size_t)NW,
                                   bq, (float*)pq, MROWS, HID);
    gemm_mma<<<gG, 256, GM_SMEM>>>(ah, al, wh + 1 * (size_t)NW, wl + 1 * (size_t)NW,
                                   bk, (float*)pk, MROWS, HID);
    gemm_mma<<<gG, 256, GM_SMEM>>>(ah, al, wh + 2 * (size_t)NW, wl + 2 * (size_t)NW,
                                   bv, (float*)pv, MROWS, HID);

    // q/k/v bf16 hi-lo splits for the attention mma
    conv_split<<<NX / 1024, 256>>>((const float*)pq, (__nv_bfloat16*)pqh,
                                   (__nv_bfloat16*)pql, NX);
    conv_split<<<NX / 1024, 256>>>((const float*)pk, (__nv_bfloat16*)pkh,
                                   (__nv_bfloat16*)pkl, NX);
    conv_split<<<NX / 1024, 256>>>((const float*)pv, (__nv_bfloat16*)pvh,
                                   (__nv_bfloat16*)pvl, NX);

    dim3 gAttn(SEQ / 128, BATCH * NH);  // (16, 32)
    attn_mma<<<gAttn, 256, AT_SMEM>>>(
        (const __nv_bfloat16*)pqh, (const __nv_bfloat16*)pql,
        (const __nv_bfloat16*)pkh, (const __nv_bfloat16*)pkl,
        (const __nv_bfloat16*)pvh, (const __nv_bfloat16*)pvl,
        attn, (float*)pctx);

    conv_split<<<NX / 1024, 256>>>((const float*)pctx, ah, al, NX);
    gemm_mma<<<gG, 256, GM_SMEM>>>(ah, al, wh + 3 * (size_t)NW, wl + 3 * (size_t)NW,
                                   bo, out, MROWS, HID);
}

// round 13
// speedup vs baseline: 3.1553x; 1.0726x over previous
#include <cuda_runtime.h>
#include <cuda_bf16.h>
#include <cstdint>
#include <math.h>

// Problem constants
#define BATCH 2
#define SEQ   2048
#define HID   1024
#define NH    16
#define HD    64
#define MROWS (BATCH * SEQ)   // 4096

static const size_t OUT_ELEMS  = (size_t)BATCH * SEQ * HID;              // 4,194,304
static const size_t ATTN_ELEMS = (size_t)BATCH * NH * SEQ * (size_t)SEQ; // 134,217,728

// Scratch (allocation-free: __device__ globals)
__device__ __align__(16) float g_attn_scratch[(size_t)BATCH * NH * SEQ * (size_t)SEQ];

// bf16 hi/lo splits
__device__ __align__(16) __nv_bfloat16 g_ah[MROWS * HID];   // x hi
__device__ __align__(16) __nv_bfloat16 g_al[MROWS * HID];   // x lo
__device__ __align__(16) __nv_bfloat16 g_wh[4 * HID * HID]; // weights hi (q,k,v,o)
__device__ __align__(16) __nv_bfloat16 g_wl[4 * HID * HID]; // weights lo
__device__ __align__(16) __nv_bfloat16 g_qh[MROWS * HID];
__device__ __align__(16) __nv_bfloat16 g_ql[MROWS * HID];
__device__ __align__(16) __nv_bfloat16 g_kh[MROWS * HID];
__device__ __align__(16) __nv_bfloat16 g_kl[MROWS * HID];
__device__ __align__(16) __nv_bfloat16 g_vh[MROWS * HID];
__device__ __align__(16) __nv_bfloat16 g_vl[MROWS * HID];
__device__ __align__(16) __nv_bfloat16 g_cth[MROWS * HID];  // ctx hi
__device__ __align__(16) __nv_bfloat16 g_ctl[MROWS * HID];  // ctx lo

// ---------------------------------------------------------------------------
// PTX helpers (sm_80-baseline features only)
// ---------------------------------------------------------------------------
__device__ __forceinline__ uint32_t smem_u32(const void* p) {
    uint32_t a;
    asm("{ .reg .u64 t; cvta.to.shared.u64 t, %1; cvt.u32.u64 %0, t; }" : "=r"(a) : "l"(p));
    return a;
}

#define CP_ASYNC16(dst, src) \
    asm volatile("cp.async.cg.shared.global [%0], [%1], 16;" :: "r"(dst), "l"(src) : "memory")
#define CP_COMMIT() asm volatile("cp.async.commit_group;" ::: "memory")
#define CP_WAIT(N)  asm volatile("cp.async.wait_group %0;" :: "n"(N) : "memory")

#define LDM4(r, a)                                                              \
    asm volatile("ldmatrix.sync.aligned.m8n8.x4.shared.b16 {%0,%1,%2,%3}, [%4];" \
                 : "=r"((r)[0]), "=r"((r)[1]), "=r"((r)[2]), "=r"((r)[3]) : "r"(a))

#define LDM4T(r, a)                                                                   \
    asm volatile("ldmatrix.sync.aligned.m8n8.x4.trans.shared.b16 {%0,%1,%2,%3}, [%4];" \
                 : "=r"((r)[0]), "=r"((r)[1]), "=r"((r)[2]), "=r"((r)[3]) : "r"(a))

#define MMA16816(c, a, b0, b1)                                                  \
    asm volatile("mma.sync.aligned.m16n8k16.row.col.f32.bf16.bf16.f32 "         \
                 "{%0,%1,%2,%3}, {%4,%5,%6,%7}, {%8,%9}, {%0,%1,%2,%3};"        \
                 : "+f"((c)[0]), "+f"((c)[1]), "+f"((c)[2]), "+f"((c)[3])       \
                 : "r"((a)[0]), "r"((a)[1]), "r"((a)[2]), "r"((a)[3]),          \
                   "r"(b0), "r"(b1))

__device__ __forceinline__ float ex2f(float x) {
    float r; asm("ex2.approx.f32 %0, %1;" : "=f"(r) : "f"(x)); return r;
}
__device__ __forceinline__ void split2(float x, float y, uint32_t& hi, uint32_t& lo) {
    __nv_bfloat16 hx = __float2bfloat16(x), hy = __float2bfloat16(y);
    __nv_bfloat162 hp(hx, hy);
    hi = *(uint32_t*)&hp;
    __nv_bfloat162 lp = __floats2bfloat162_rn(x - __bfloat162float(hx),
                                              y - __bfloat162float(hy));
    lo = *(uint32_t*)&lp;
}

// ---------------------------------------------------------------------------
// fp32 -> bf16 hi/lo split (x and weights only — everything else is fused)
// ---------------------------------------------------------------------------
__global__ __launch_bounds__(256) void conv_split(
    const float* __restrict__ src, __nv_bfloat16* __restrict__ hi,
    __nv_bfloat16* __restrict__ lo, int n)
{
    int i = (blockIdx.x * 256 + threadIdx.x) * 4;
    if (i >= n) return;
    float4 v = *(const float4*)&src[i];
    __nv_bfloat16 h0 = __float2bfloat16(v.x), h1 = __float2bfloat16(v.y);
    __nv_bfloat16 h2 = __float2bfloat16(v.z), h3 = __float2bfloat16(v.w);
    __nv_bfloat16 l0 = __float2bfloat16(v.x - __bfloat162float(h0));
    __nv_bfloat16 l1 = __float2bfloat16(v.y - __bfloat162float(h1));
    __nv_bfloat16 l2 = __float2bfloat16(v.z - __bfloat162float(h2));
    __nv_bfloat16 l3 = __float2bfloat16(v.w - __bfloat162float(h3));
    *(__nv_bfloat162*)&hi[i]     = __nv_bfloat162(h0, h1);
    *(__nv_bfloat162*)&hi[i + 2] = __nv_bfloat162(h2, h3);
    *(__nv_bfloat162*)&lo[i]     = __nv_bfloat162(l0, l1);
    *(__nv_bfloat162*)&lo[i + 2] = __nv_bfloat162(l2, l3);
}

// ---------------------------------------------------------------------------
// Tensor-core (mma.sync bf16) 3-split GEMM:
//   acc = Ah@Bh^T + Ah@Bl^T + Al@Bh^T + bias
// EMODE 0: write fp32 C.  EMODE 1: write bf16 hi/lo pair (fused conv_split).
// ---------------------------------------------------------------------------
#define GM_STEPS (HID / 32)
#define GM_TPAD  80
#define GM_TILE  (128 * GM_TPAD)
#define GM_BUF   (4 * GM_TILE)
#define GM_SMEM  (2 * GM_BUF)

template <int EMODE>
__global__ __launch_bounds__(256, 2) void gemm_mma(
    const __nv_bfloat16* __restrict__ Ah, const __nv_bfloat16* __restrict__ Al,
    const __nv_bfloat16* __restrict__ Bh, const __nv_bfloat16* __restrict__ Bl,
    const float* __restrict__ bias, float* __restrict__ Cf,
    __nv_bfloat16* __restrict__ Ch, __nv_bfloat16* __restrict__ Cl,
    int M, int N)
{
    extern __shared__ __align__(128) char sm[];
    const uint32_t smb = smem_u32(sm);
    const int tid = threadIdx.x;
    const int lane = tid & 31, w = tid >> 5;
    const int wr = w >> 2;
    const int wc = w & 3;
    const int m0 = blockIdx.y * 128, n0 = blockIdx.x * 128;
    const int K = HID;

    const __nv_bfloat16* gb[4] = {
        Ah + (size_t)m0 * K, Al + (size_t)m0 * K,
        Bh + (size_t)n0 * K, Bl + (size_t)n0 * K };

    auto load_step = [&](int b, int k0) {
        uint32_t bufb = smb + b * GM_BUF;
        #pragma unroll
        for (int j = 0; j < 8; j++) {
            int i = tid + j * 256;
            int t = i >> 9;
            int r = (i >> 2) & 127;
            int c = i & 3;
            const __nv_bfloat16* src = gb[t] + (size_t)r * K + k0 + c * 8;
            uint32_t dst = bufb + t * GM_TILE + r * GM_TPAD + c * 16;
            CP_ASYNC16(dst, src);
        }
    };

    float acc[4][4][4];
    #pragma unroll
    for (int mi = 0; mi < 4; mi++)
        #pragma unroll
        for (int nt = 0; nt < 4; nt++)
            #pragma unroll
            for (int r = 0; r < 4; r++) acc[mi][nt][r] = 0.f;

    const uint32_t a_off = (uint32_t)(wr * 64 + (lane & 15)) * GM_TPAD + (lane >> 4) * 16;
    const int q = lane >> 3;
    const uint32_t b_off = (uint32_t)(wc * 32 + (q >> 1) * 8 + (lane & 7)) * GM_TPAD
                         + (q & 1) * 16;

    load_step(0, 0);
    CP_COMMIT();

    for (int t = 0; t < GM_STEPS; t++) {
        if (t + 1 < GM_STEPS) {
            load_step((t + 1) & 1, (t + 1) * 32);
            CP_COMMIT();
            CP_WAIT(1);
        } else {
            CP_WAIT(0);
        }
        __syncthreads();

        const uint32_t bb = smb + (t & 1) * GM_BUF;
        #pragma unroll
        for (int kk = 0; kk < 2; kk++) {
            const uint32_t kb = kk * 32;
            uint32_t af[4][4], bh[4][2], bl[4][2];

            #pragma unroll
            for (int p = 0; p < 2; p++) {
                uint32_t rb = bb + 2 * GM_TILE + b_off + p * 16 * GM_TPAD + kb;
                uint32_t tmp[4];
                LDM4(tmp, rb);
                bh[2 * p][0] = tmp[0]; bh[2 * p][1] = tmp[1];
                bh[2 * p + 1][0] = tmp[2]; bh[2 * p + 1][1] = tmp[3];
                LDM4(tmp, rb + GM_TILE);
                bl[2 * p][0] = tmp[0]; bl[2 * p][1] = tmp[1];
                bl[2 * p + 1][0] = tmp[2]; bl[2 * p + 1][1] = tmp[3];
            }

            #pragma unroll
            for (int mi = 0; mi < 4; mi++) {
                LDM4(af[mi], bb + a_off + (uint32_t)mi * 16 * GM_TPAD + kb);
            }
            #pragma unroll
            for (int mi = 0; mi < 4; mi++)
                #pragma unroll
                for (int nt = 0; nt < 4; nt++) {
                    MMA16816(acc[mi][nt], af[mi], bh[nt][0], bh[nt][1]);
                    MMA16816(acc[mi][nt], af[mi], bl[nt][0], bl[nt][1]);
                }

            #pragma unroll
            for (int mi = 0; mi < 4; mi++) {
                LDM4(af[mi], bb + GM_TILE + a_off + (uint32_t)mi * 16 * GM_TPAD + kb);
            }
            #pragma unroll
            for (int mi = 0; mi < 4; mi++)
                #pragma unroll
                for (int nt = 0; nt < 4; nt++)
                    MMA16816(acc[mi][nt], af[mi], bh[nt][0], bh[nt][1]);
        }
        __syncthreads();
    }

    const int rbase = m0 + wr * 64 + (lane >> 2);
    #pragma unroll
    for (int nt = 0; nt < 4; nt++) {
        const int col = n0 + wc * 32 + nt * 8 + (lane & 3) * 2;
        const float2 bv = *(const float2*)&bias[col];
        #pragma unroll
        for (int mi = 0; mi < 4; mi++) {
            int r0 = rbase + mi * 16;
            float v00 = acc[mi][nt][0] + bv.x, v01 = acc[mi][nt][1] + bv.y;
            float v10 = acc[mi][nt][2] + bv.x, v11 = acc[mi][nt][3] + bv.y;
            if (EMODE == 0) {
                *(float2*)&Cf[(size_t)r0 * N + col]       = make_float2(v00, v01);
                *(float2*)&Cf[(size_t)(r0 + 8) * N + col] = make_float2(v10, v11);
            } else {
                uint32_t hi, lo;
                split2(v00, v01, hi, lo);
                *(uint32_t*)&Ch[(size_t)r0 * N + col] = hi;
                *(uint32_t*)&Cl[(size_t)r0 * N + col] = lo;
                split2(v10, v11, hi, lo);
                *(uint32_t*)&Ch[(size_t)(r0 + 8) * N + col] = hi;
                *(uint32_t*)&Cl[(size_t)(r0 + 8) * N + col] = lo;
            }
        }
    }
}

// ---------------------------------------------------------------------------
// Tensor-core causal flash attention (mma.sync, bf16 3-split).
// CTA: 256 threads = 8 warps; Q row tile 128 (warp = 16 rows); j-tile 64.
// Phase 1: S = QK^T (3-term), online (m, l) stats only.
// Phase 2: recompute S, p = exp2(s*C - m)/l, write P, ctx += P@V (3-term).
// ctx emitted directly as bf16 hi/lo for the O-projection.
// ---------------------------------------------------------------------------
#define AT_STRIDE 144
#define AT_QTILE  (128 * AT_STRIDE)
#define AT_Q      (2 * AT_QTILE)
#define AT_KVT    (64 * AT_STRIDE)
#define AT_KVBUF  (4 * AT_KVT)
#define AT_SMEM   (AT_Q + 2 * AT_KVBUF)
#define C_SCALE   11.5415603270f         // 8 * log2(e)

__global__ __launch_bounds__(256) void attn_mma(
    const __nv_bfloat16* __restrict__ qh, const __nv_bfloat16* __restrict__ ql,
    const __nv_bfloat16* __restrict__ kh, const __nv_bfloat16* __restrict__ kl,
    const __nv_bfloat16* __restrict__ vh, const __nv_bfloat16* __restrict__ vl,
    float* __restrict__ attn,
    __nv_bfloat16* __restrict__ cth, __nv_bfloat16* __restrict__ ctl)
{
    extern __shared__ __align__(1024) char smc[];
    const uint32_t smb = smem_u32(smc);
    const int tid = threadIdx.x, lane = tid & 31, w = tid >> 5;
    const int mt = (int)gridDim.x - 1 - (int)blockIdx.x;   // heavy-first
    const int bh = blockIdx.y, b = bh >> 4, h = bh & 15;
    const int m0 = mt * 128;
    const int njt = 2 * mt + 2;
    const size_t hoff = (size_t)b * SEQ * HID + h * 64;
    const __nv_bfloat16* src[6] = { qh + hoff, ql + hoff, kh + hoff,
                                    kl + hoff, vh + hoff, vl + hoff };
    float* arow = attn + (size_t)bh * SEQ * SEQ;

    for (int i = tid; i < 2048; i += 256) {
        int t = i >> 10, r = (i >> 3) & 127, c = i & 7;
        CP_ASYNC16(smb + t * AT_QTILE + r * AT_STRIDE + c * 16,
                   src[t] + (size_t)(m0 + r) * HID + c * 8);
    }
    CP_COMMIT();

    auto load_kv = [&](int buf, int jt, int ntiles) {
        uint32_t base = smb + AT_Q + buf * AT_KVBUF;
        int j0 = jt * 64;
        for (int i = tid; i < ntiles * 512; i += 256) {
            int t = i >> 9, r = (i >> 3) & 63, c = i & 7;
            CP_ASYNC16(base + t * AT_KVT + r * AT_STRIDE + c * 16,
                       src[2 + t] + (size_t)(j0 + r) * HID + c * 8);
        }
    };

    const int wq = w * 16;
    const uint32_t qa  = smb + (uint32_t)(wq + (lane & 15)) * AT_STRIDE + (lane >> 4) * 16;
    const int q2 = lane >> 3;
    const uint32_t kfo = (uint32_t)((q2 >> 1) * 8 + (lane & 7)) * AT_STRIDE + (q2 & 1) * 16;
    const int rbase = m0 + wq + (lane >> 2);

    uint32_t qhf[4][4];
    bool qloaded = false;

    auto compute_S = [&](uint32_t kb, float (*sacc)[4]) {
        #pragma unroll
        for (int nt = 0; nt < 8; nt++)
            #pragma unroll
            for (int r = 0; r < 4; r++) sacc[nt][r] = 0.f;
        #pragma unroll
        for (int kt = 0; kt < 4; kt++) {
            uint32_t qlf[4];
            LDM4(qlf, qa + AT_QTILE + kt * 32);
            #pragma unroll
            for (int p = 0; p < 4; p++) {
                uint32_t kh4[4], kl4[4];
                uint32_t ka = kb + kfo + (uint32_t)p * 16 * AT_STRIDE + kt * 32;
                LDM4(kh4, ka);
                LDM4(kl4, ka + AT_KVT);
                MMA16816(sacc[2 * p],     qhf[kt], kh4[0], kh4[1]);
                MMA16816(sacc[2 * p + 1], qhf[kt], kh4[2], kh4[3]);
                MMA16816(sacc[2 * p],     qhf[kt], kl4[0], kl4[1]);
                MMA16816(sacc[2 * p + 1], qhf[kt], kl4[2], kl4[3]);
                MMA16816(sacc[2 * p],     qlf, kh4[0], kh4[1]);
                MMA16816(sacc[2 * p + 1], qlf, kh4[2], kh4[3]);
            }
        }
    };

    float m_[2] = { -1e30f, -1e30f };
    float l_[2] = { 0.f, 0.f };

    // ---------------- phase 1: stats ----------------
    load_kv(0, 0, 2);
    CP_COMMIT();
    for (int jt = 0; jt < njt; jt++) {
        if (jt + 1 < njt) { load_kv((jt + 1) & 1, jt + 1, 2); CP_COMMIT(); CP_WAIT(1); }
        else              { CP_WAIT(0); }
        __syncthreads();
        if (!qloaded) {
            qloaded = true;
            #pragma unroll
            for (int kt = 0; kt < 4; kt++) LDM4(qhf[kt], qa + kt * 32);
        }

        const uint32_t kb = smb + AT_Q + (jt & 1) * AT_KVBUF;
        float sacc[8][4];
        compute_S(kb, sacc);

        const int colb = jt * 64 + (lane & 3) * 2;
        #pragma unroll
        for (int hf = 0; hf < 2; hf++) {
            const int row = rbase + 8 * hf;
            float sv[16];
            float tmax = -1e30f;
            #pragma unroll
            for (int nt = 0; nt < 8; nt++) {
                int c0 = colb + nt * 8;
                float s0 = (c0     > row) ? -1e30f : sacc[nt][2 * hf]     * C_SCALE;
                float s1 = (c0 + 1 > row) ? -1e30f : sacc[nt][2 * hf + 1] * C_SCALE;
                sv[2 * nt] = s0; sv[2 * nt + 1] = s1;
                tmax = fmaxf(tmax, fmaxf(s0, s1));
            }
            tmax = fmaxf(tmax, __shfl_xor_sync(0xffffffffu, tmax, 1));
            tmax = fmaxf(tmax, __shfl_xor_sync(0xffffffffu, tmax, 2));
            float mnew = fmaxf(m_[hf], tmax);
            float s = 0.f;
            #pragma unroll
            for (int e = 0; e < 16; e++) s += ex2f(sv[e] - mnew);
            s += __shfl_xor_sync(0xffffffffu, s, 1);
            s += __shfl_xor_sync(0xffffffffu, s, 2);
            l_[hf] = l_[hf] * ex2f(m_[hf] - mnew) + s;
            m_[hf] = mnew;
        }
        __syncthreads();
    }

    const float invl[2] = { 1.f / l_[0], 1.f / l_[1] };

    // ---------------- phase 2: P + PV ----------------
    float cacc[8][4];
    #pragma unroll
    for (int nt = 0; nt < 8; nt++)
        #pragma unroll
        for (int r = 0; r < 4; r++) cacc[nt][r] = 0.f;

    load_kv(0, 0, 4);
    CP_COMMIT();
    for (int jt = 0; jt < njt; jt++) {
        if (jt + 1 < njt) { load_kv((jt + 1) & 1, jt + 1, 4); CP_COMMIT(); CP_WAIT(1); }
        else              { CP_WAIT(0); }
        __syncthreads();

        const uint32_t kb = smb + AT_Q + (jt & 1) * AT_KVBUF;
        float sacc[8][4];
        compute_S(kb, sacc);

        const int colb = jt * 64 + (lane & 3) * 2;
        uint32_t aph[4][4], apl[4][4];
        #pragma unroll
        for (int nt = 0; nt < 8; nt++) {
            int c0 = colb + nt * 8;
            int kj = nt >> 1, sub = nt & 1;
            #pragma unroll
            for (int hf = 0; hf < 2; hf++) {
                const int row = rbase + 8 * hf;
                float p0 = (c0     > row) ? 0.f
                         : ex2f(fmaf(sacc[nt][2 * hf],     C_SCALE, -m_[hf])) * invl[hf];
                float p1 = (c0 + 1 > row) ? 0.f
                         : ex2f(fmaf(sacc[nt][2 * hf + 1], C_SCALE, -m_[hf])) * invl[hf];
                *(float2*)&arow[(size_t)row * SEQ + c0] = make_float2(p0, p1);
                split2(p0, p1, aph[kj][sub * 2 + hf], apl[kj][sub * 2 + hf]);
            }
        }

        const uint32_t vb = kb + 2 * AT_KVT;
        const uint32_t vfo = vb + (uint32_t)(lane & 15) * AT_STRIDE + (lane >> 4) * 16;
        #pragma unroll
        for (int kj = 0; kj < 4; kj++) {
            #pragma unroll
            for (int dp = 0; dp < 4; dp++) {
                uint32_t vh4[4], vl4[4];
                uint32_t va = vfo + (uint32_t)kj * 16 * AT_STRIDE + dp * 32;
                LDM4T(vh4, va);
                LDM4T(vl4, va + AT_KVT);
                MMA16816(cacc[2 * dp],     aph[kj], vh4[0], vh4[1]);
                MMA16816(cacc[2 * dp + 1], aph[kj], vh4[2], vh4[3]);
                MMA16816(cacc[2 * dp],     aph[kj], vl4[0], vl4[1]);
                MMA16816(cacc[2 * dp + 1], aph[kj], vl4[2], vl4[3]);
                MMA16816(cacc[2 * dp],     apl[kj], vh4[0], vh4[1]);
                MMA16816(cacc[2 * dp + 1], apl[kj], vh4[2], vh4[3]);
            }
        }
        __syncthreads();
    }

    // ctx write — fused bf16 hi/lo split
    #pragma unroll
    for (int hf = 0; hf < 2; hf++) {
        const int row = rbase + 8 * hf;
        size_t off = ((size_t)b * SEQ + row) * HID + h * 64 + (lane & 3) * 2;
        #pragma unroll
        for (int nt = 0; nt < 8; nt++) {
            uint32_t hi, lo;
            split2(cacc[nt][2 * hf], cacc[nt][2 * hf + 1], hi, lo);
            *(uint32_t*)&cth[off + nt * 8] = hi;
            *(uint32_t*)&ctl[off + nt * 8] = lo;
        }
    }

    // zero-fill fully masked columns
    const int zstart = m0 + 128;
    const int zc = SEQ - zstart;
    if (zc > 0) {
        const int nv = zc >> 2;
        for (int it = tid; it < 128 * nv; it += 256) {
            int r = it / nv, c = it - r * nv;
            *(float4*)&arow[(size_t)(m0 + r) * SEQ + zstart + c * 4] =
                make_float4(0.f, 0.f, 0.f, 0.f);
        }
    }
}

// ---------------------------------------------------------------------------
extern "C" void kernel_launch(void* const* d_in, const int* in_sizes, int n_in,
                              void* d_out, int out_size)
{
    const float* x  = (const float*)d_in[0];
    const float* Wq = (const float*)d_in[1];
    const float* bq = (const float*)d_in[2];
    const float* Wk = (const float*)d_in[3];
    const float* bk = (const float*)d_in[4];
    const float* Wv = (const float*)d_in[5];
    const float* bv = (const float*)d_in[6];
    const float* Wo = (const float*)d_in[7];
    const float* bo = (const float*)d_in[8];

    float* out = (float*)d_out;

    void *pattn, *pah, *pal, *pwh, *pwl;
    void *pqh, *pql, *pkh, *pkl, *pvh, *pvl, *pcth, *pctl;
    cudaGetSymbolAddress(&pattn, g_attn_scratch);
    cudaGetSymbolAddress(&pah, g_ah);
    cudaGetSymbolAddress(&pal, g_al);
    cudaGetSymbolAddress(&pwh, g_wh);
    cudaGetSymbolAddress(&pwl, g_wl);
    cudaGetSymbolAddress(&pqh, g_qh);
    cudaGetSymbolAddress(&pql, g_ql);
    cudaGetSymbolAddress(&pkh, g_kh);
    cudaGetSymbolAddress(&pkl, g_kl);
    cudaGetSymbolAddress(&pvh, g_vh);
    cudaGetSymbolAddress(&pvl, g_vl);
    cudaGetSymbolAddress(&pcth, g_cth);
    cudaGetSymbolAddress(&pctl, g_ctl);

    __nv_bfloat16* ah = (__nv_bfloat16*)pah;
    __nv_bfloat16* al = (__nv_bfloat16*)pal;
    __nv_bfloat16* wh = (__nv_bfloat16*)pwh;
    __nv_bfloat16* wl = (__nv_bfloat16*)pwl;

    float* attn = ((size_t)out_size >= OUT_ELEMS + ATTN_ELEMS)
                      ? out + OUT_ELEMS
                      : (float*)pattn;

    cudaFuncSetAttribute(gemm_mma<0>, cudaFuncAttributeMaxDynamicSharedMemorySize, GM_SMEM);
    cudaFuncSetAttribute(gemm_mma<1>, cudaFuncAttributeMaxDynamicSharedMemorySize, GM_SMEM);
    cudaFuncSetAttribute(attn_mma, cudaFuncAttributeMaxDynamicSharedMemorySize, AT_SMEM);

    const int NW = HID * HID;    // 1,048,576
    const int NX = MROWS * HID;  // 4,194,304

    // input splits (x + 4 weights only)
    conv_split<<<NX / 1024, 256>>>(x, ah, al, NX);
    conv_split<<<NW / 1024, 256>>>(Wq, wh + 0 * (size_t)NW, wl + 0 * (size_t)NW, NW);
    conv_split<<<NW / 1024, 256>>>(Wk, wh + 1 * (size_t)NW, wl + 1 * (size_t)NW, NW);
    conv_split<<<NW / 1024, 256>>>(Wv, wh + 2 * (size_t)NW, wl + 2 * (size_t)NW, NW);
    conv_split<<<NW / 1024, 256>>>(Wo, wh + 3 * (size_t)NW, wl + 3 * (size_t)NW, NW);

    dim3 gG(HID / 128, MROWS / 128);  // (8, 32)
    // Q/K/V projections: bf16 hi/lo emitted directly (EMODE 1)
    gemm_mma<1><<<gG, 256, GM_SMEM>>>(ah, al, wh + 0 * (size_t)NW, wl + 0 * (size_t)NW,
                                      bq, nullptr,
                                      (__nv_bfloat16*)pqh, (__nv_bfloat16*)pql, MROWS, HID);
    gemm_mma<1><<<gG, 256, GM_SMEM>>>(ah, al, wh + 1 * (size_t)NW, wl + 1 * (size_t)NW,
                                      bk, nullptr,
                                      (__nv_bfloat16*)pkh, (__nv_bfloat16*)pkl, MROWS, HID);
    gemm_mma<1><<<gG, 256, GM_SMEM>>>(ah, al, wh + 2 * (size_t)NW, wl + 2 * (size_t)NW,
                                      bv, nullptr,
                                      (__nv_bfloat16*)pvh, (__nv_bfloat16*)pvl, MROWS, HID);

    dim3 gAttn(SEQ / 128, BATCH * NH);  // (16, 32)
    attn_mma<<<gAttn, 256, AT_SMEM>>>(
        (const __nv_bfloat16*)pqh, (const __nv_bfloat16*)pql,
        (const __nv_bfloat16*)pkh, (const __nv_bfloat16*)pkl,
        (const __nv_bfloat16*)pvh, (const __nv_bfloat16*)pvl,
        attn, (__nv_bfloat16*)pcth, (__nv_bfloat16*)pctl);

    // O projection consumes fused ctx hi/lo, writes fp32 out (EMODE 0)
    gemm_mma<0><<<gG, 256, GM_SMEM>>>((const __nv_bfloat16*)pcth, (const __nv_bfloat16*)pctl,
                                      wh + 3 * (size_t)NW, wl + 3 * (size_t)NW,
                                      bo, out, nullptr, nullptr, MROWS, HID);
}